// round 3
// baseline (speedup 1.0000x reference)
#include <cuda_runtime.h>

// GraphAttention collapsed form (validated: rel_err ~2e-7):
//   v[b,n] = x[b, NEF + n]
//   c1 = W.a[:64], c2 = W.a[64:]   (scalars)
//   w(i,o) = exp(lrelu(c1*v[i] + c2*v[(i+o)%N])),  o in [0,17)
//   denom[b] = sum_{i,o} w(i,o)
//   s[b,i]   = sum_o w(i,o)*v[(i+o)%N]
//   out[b,i,f] = lrelu(W[f]*s[b,i]) / denom[b]   (lrelu pos-homogeneous, denom>0)
//
// One kernel. Per-batch decoupled lookback instead of a grid barrier:
// 32 blocks/batch publish partial denominators; the last arriver (per-batch
// atomic counter) sums them in fixed order, publishes 1/denom, bumps a
// monotone release word. Waiters poll with plain volatile loads (no atomic
// hammering on the L2 line). Self-resetting -> graph-replay safe.

#define NB      8
#define NN      4096
#define NOFF    17
#define FOUT    64
#define NEF     4096
#define BPB     32            // blocks per batch
#define BNODES  128           // nodes per block
#define GRID    (NB * BPB)    // 256 blocks; 8 warps each -> fully co-resident

__device__ float        g_part[GRID];
__device__ float        g_inv[NB];
__device__ unsigned int g_ctr[NB];   // zero-init; reset by releaser each replay
__device__ unsigned int g_rel[NB];   // monotone release counter per batch

__device__ __forceinline__ float lrelu(float x) { return x > 0.0f ? x : 0.01f * x; }

__device__ __forceinline__ float warp_sum(float p) {
#pragma unroll
    for (int off = 16; off > 0; off >>= 1)
        p += __shfl_down_sync(0xffffffffu, p, off);
    return p;
}

__global__ void __launch_bounds__(256, 4)
ga_fused(const float* __restrict__ x,
         const float* __restrict__ W,
         const float* __restrict__ a,
         float* __restrict__ out) {
    __shared__ float sv[BNODES + 16];
    __shared__ float ssn[BNODES];
    __shared__ float sW[FOUT];
    __shared__ float sred[4];
    __shared__ float sc[2];
    __shared__ float sinv;
    __shared__ unsigned int srel0;

    const int b     = blockIdx.x >> 5;
    const int chunk = blockIdx.x & (BPB - 1);
    const int base  = chunk * BNODES;
    const float* v  = x + (size_t)b * (NEF + NN) + NEF;
    const int t    = threadIdx.x;
    const int warp = t >> 5;
    const int lane = t & 31;

    // Release baseline must be read before this block's arrival is counted.
    if (t == 0) srel0 = *((volatile unsigned int*)&g_rel[b]);

    // Disjoint warp roles before the first sync:
    //   t 0..143      : load node values
    //   warp 5        : c1 = W . a[:64]   (shuffle reduce)
    //   warp 6        : c2 = W . a[64:]
    //   warp 7        : load W into smem
    if (t < BNODES + 16) sv[t] = v[(base + t) & (NN - 1)];
    if (warp == 5) {
        float p = fmaf(W[lane], a[lane], W[lane + 32] * a[lane + 32]);
        p = warp_sum(p);
        if (lane == 0) sc[0] = p;
    } else if (warp == 6) {
        float p = fmaf(W[lane], a[64 + lane], W[lane + 32] * a[96 + lane]);
        p = warp_sum(p);
        if (lane == 0) sc[1] = p;
    } else if (warp == 7) {
        sW[lane]      = W[lane];
        sW[lane + 32] = W[lane + 32];
    }
    __syncthreads();

    // Phase 1: per-node numerator s and thread-local exp-sum.
    const float c1 = sc[0], c2 = sc[1];
    float esum = 0.0f;
    if (t < BNODES) {
        const float vi = sv[t];
        float s = 0.0f;
#pragma unroll
        for (int o = 0; o < NOFF; o++) {
            const float vj = sv[t + o];
            const float w  = __expf(lrelu(fmaf(c1, vi, c2 * vj)));
            esum += w;
            s    += w * vj;
        }
        ssn[t] = s;
    }

    // Block-reduce esum: warps 0..3 shuffle-reduce, combine on t0.
    if (warp < 4) {
        const float ws = warp_sum(esum);
        if (lane == 0) sred[warp] = ws;
    }
    __syncthreads();

    // Publish partial, per-batch lookback.
    if (t == 0) {
        const float blk = (sred[0] + sred[1]) + (sred[2] + sred[3]);
        g_part[blockIdx.x] = blk;
        __threadfence();
        const unsigned int old = atomicAdd(&g_ctr[b], 1u);
        if (old == BPB - 1) {
            // Last arriver: all 32 partials are globally visible.
            float d = 0.0f;
#pragma unroll
            for (int k = 0; k < BPB; k++) d += __ldcg(&g_part[b * BPB + k]);
            const float inv = 1.0f / d;
            g_inv[b]  = inv;
            g_ctr[b]  = 0;                 // reset for next replay
            __threadfence();
            *((volatile unsigned int*)&g_rel[b]) = srel0 + 1u;
            sinv = inv;
        } else {
            while (*((volatile unsigned int*)&g_rel[b]) == srel0)
                __nanosleep(32);
            __threadfence();
            sinv = *((volatile float*)&g_inv[b]);
        }
    }
    __syncthreads();

    // Phase 2: 128 nodes x 64 feats = 2048 float4, fully coalesced.
    const float inv = sinv;
    float4* o4 = (float4*)(out + ((size_t)b * NN + base) * FOUT);
    const float4* w4 = (const float4*)sW;
#pragma unroll
    for (int k = 0; k < 8; k++) {
        const int idx  = t + k * 256;   // 0..2047
        const int node = idx >> 4;
        const int f4   = idx & 15;
        const float s  = ssn[node];
        const float4 w = w4[f4];
        float4 r;
        r.x = lrelu(s * w.x) * inv;
        r.y = lrelu(s * w.y) * inv;
        r.z = lrelu(s * w.z) * inv;
        r.w = lrelu(s * w.w) * inv;
        o4[idx] = r;
    }
}

extern "C" void kernel_launch(void* const* d_in, const int* in_sizes, int n_in,
                              void* d_out, int out_size) {
    const float* x = (const float*)d_in[0];
    const float* W = (const float*)d_in[1];
    const float* a = (const float*)d_in[2];
    float* out = (float*)d_out;

    ga_fused<<<GRID, 256>>>(x, W, a, out);
}

// round 4
// speedup vs baseline: 1.2657x; 1.2657x over previous
#include <cuda_runtime.h>
#include <cstdint>

// GraphAttention collapsed form (validated rounds 1-3, rel_err ~2e-7):
//   v[b,n] = x[b, NEF + n]
//   c1 = W.a[:64], c2 = W.a[64:]   (scalars)
//   w(i,o) = exp(lrelu(c1*v[i] + c2*v[(i+o)%N])),  o in [0,17)
//   denom[b] = sum_{i,o} w(i,o)
//   s[b,i]   = sum_o w(i,o)*v[(i+o)%N]
//   out[b,i,f] = lrelu(W[f]*s[b,i]) / denom[b]
//
// R4: one kernel, 8-CTA clusters (1 cluster == 1 batch). Batch-wide
// denominator exchanged through DSMEM + barrier.cluster instead of
// global-memory atomics/polling (removes serial L2/DRAM round trips).

#define NB      8
#define NN      4096
#define NOFF    17
#define FOUT    64
#define NEF     4096
#define CPB     8             // CTAs per batch == cluster size
#define TPB     512
#define BNODES  512           // nodes per CTA (CPB*BNODES == NN)
#define GRID    (NB * CPB)    // 64 CTAs

__device__ __forceinline__ float lrelu(float x) { return x > 0.0f ? x : 0.01f * x; }

__device__ __forceinline__ float warp_sum(float p) {
#pragma unroll
    for (int off = 16; off > 0; off >>= 1)
        p += __shfl_down_sync(0xffffffffu, p, off);
    return p;
}

__device__ __forceinline__ uint32_t smem_u32(const void* p) {
    uint32_t r;
    asm("{ .reg .u64 t; cvta.to.shared.u64 t, %1; cvt.u32.u64 %0, t; }"
        : "=r"(r) : "l"(p));
    return r;
}

__global__ void __launch_bounds__(TPB, 1) __cluster_dims__(CPB, 1, 1)
ga_fused(const float* __restrict__ x,
         const float* __restrict__ W,
         const float* __restrict__ a,
         float* __restrict__ out) {
    __shared__ float sv[BNODES + 16];
    __shared__ float ssn[BNODES];
    __shared__ float sW[FOUT];
    __shared__ float sred[16];
    __shared__ float sc[2];
    __shared__ float spart;      // this CTA's denom partial (DSMEM-visible)
    __shared__ float sinv;

    const int b    = blockIdx.x >> 3;        // batch
    const int rank = blockIdx.x & (CPB - 1); // CTA within cluster
    const int base = rank * BNODES;
    const float* v = x + (size_t)b * (NEF + NN) + NEF;
    const int t    = threadIdx.x;
    const int warp = t >> 5;
    const int lane = t & 31;

    // Parallel prologue (disjoint extra roles on high warps):
    sv[t] = v[(base + t) & (NN - 1)];
    if (t < 16) sv[BNODES + t] = v[(base + BNODES + t) & (NN - 1)];
    if (warp == 14) {            // c1 = W . a[:64]
        float p = fmaf(W[lane], a[lane], W[lane + 32] * a[lane + 32]);
        p = warp_sum(p);
        if (lane == 0) sc[0] = p;
    } else if (warp == 15) {     // c2 = W . a[64:]
        float p = fmaf(W[lane], a[64 + lane], W[lane + 32] * a[96 + lane]);
        p = warp_sum(p);
        if (lane == 0) sc[1] = p;
    } else if (warp == 13) {
        sW[lane]      = W[lane];
        sW[lane + 32] = W[lane + 32];
    }
    __syncthreads();

    // Phase 1: per-node numerator + thread-local exp-sum (1 node / thread).
    const float c1 = sc[0], c2 = sc[1];
    const float vi = sv[t];
    float esum = 0.0f, s = 0.0f;
#pragma unroll
    for (int o = 0; o < NOFF; o++) {
        const float vj = sv[t + o];
        const float w  = __expf(lrelu(fmaf(c1, vi, c2 * vj)));
        esum += w;
        s    += w * vj;
    }
    ssn[t] = s;

    const float ws = warp_sum(esum);
    if (lane == 0) sred[warp] = ws;
    __syncthreads();

    if (t == 0) {
        float p = 0.0f;
#pragma unroll
        for (int k = 0; k < 16; k++) p += sred[k];
        spart = p;
    }
    // Cluster barrier #1: publishes spart to the cluster (arrive = release).
    asm volatile("barrier.cluster.arrive.aligned;" ::: "memory");
    asm volatile("barrier.cluster.wait.aligned;"   ::: "memory");

    // Warp 0: gather all 8 partials via DSMEM, fixed-shape shuffle sum.
    if (warp == 0) {
        float p = 0.0f;
        if (lane < CPB) {
            const uint32_t laddr = smem_u32(&spart);
            uint32_t raddr;
            asm("mapa.shared::cluster.u32 %0, %1, %2;"
                : "=r"(raddr) : "r"(laddr), "r"((uint32_t)lane));
            asm volatile("ld.shared::cluster.f32 %0, [%1];"
                         : "=f"(p) : "r"(raddr));
        }
#pragma unroll
        for (int off = 4; off > 0; off >>= 1)
            p += __shfl_down_sync(0xffffffffu, p, off);
        if (lane == 0) sinv = 1.0f / p;
    }
    __syncthreads();

    // Cluster barrier #2: arrive now (DSMEM reads done), wait after stores —
    // keeps every CTA's smem alive until all peers finished reading it,
    // while the barrier latency hides under the output store drain.
    asm volatile("barrier.cluster.arrive.aligned;" ::: "memory");

    // Phase 2: 512 nodes x 64 feats = 8192 float4, fully coalesced.
    const float inv = sinv;
    float4* o4 = (float4*)(out + ((size_t)b * NN + base) * FOUT);
    const float4* w4 = (const float4*)sW;
#pragma unroll
    for (int k = 0; k < 16; k++) {
        const int idx  = t + k * TPB;   // 0..8191
        const int node = idx >> 4;
        const int f4   = idx & 15;
        const float sn = ssn[node];
        const float4 w = w4[f4];
        float4 r;
        r.x = lrelu(sn * w.x) * inv;
        r.y = lrelu(sn * w.y) * inv;
        r.z = lrelu(sn * w.z) * inv;
        r.w = lrelu(sn * w.w) * inv;
        o4[idx] = r;
    }

    asm volatile("barrier.cluster.wait.aligned;" ::: "memory");
}

extern "C" void kernel_launch(void* const* d_in, const int* in_sizes, int n_in,
                              void* d_out, int out_size) {
    const float* x = (const float*)d_in[0];
    const float* W = (const float*)d_in[1];
    const float* a = (const float*)d_in[2];
    float* out = (float*)d_out;

    ga_fused<<<GRID, TPB>>>(x, W, a, out);
}